// round 15
// baseline (speedup 1.0000x reference)
#include <cuda_runtime.h>
#include <cuda_bf16.h>
#include <cstdint>

// Shape: masks [16,512,1024,4] f32, src_stft [16,512,2048,4] f32.
// loss = mean |masks - onehot(argmax_C src_stft[:,:,:1024,:])|
// Group view: NG = 2^23 float4 pairs.
//
// CONVERGED at the dual-stream HBM ceiling (~6.05 TB/s => ~44.3 us kernel
// floor; best ncu sample 44.77 us @ 76.6% DRAM). Best e2e: 45.088 us.
// Tested and rejected over 13 rounds: __ldg vs __ldcs, grids
// 1184/1024/2048/2368, block 256 vs 512, interleaved vs batched vs
// burst-grouped loads, blocked-row addressing, identity-math epilogue.
// TMA offers no higher ceiling (LTS cap is path-independent on B300).

static constexpr int   NG      = 16 * 512 * 1024;      // 8,388,608 groups
static constexpr int   THREADS = 512;
static constexpr int   BLOCKS  = 1024;
static constexpr int   STRIDE  = THREADS * BLOCKS;     // 524,288
static constexpr int   U       = 4;
static constexpr int   OUTER   = NG / (STRIDE * U);    // 4, exact
static constexpr float INV_N   = 1.0f / 33554432.0f;   // 1 / 2^25 (exact)

__device__ float        g_partial; // zero-init at load; reset by last block each run
__device__ unsigned int g_count;

__global__ __launch_bounds__(THREADS) void recon_loss_kernel(
    const float4* __restrict__ masks,
    const float4* __restrict__ stft,
    float* __restrict__ out)
{
    const int tid = blockIdx.x * THREADS + threadIdx.x;
    float acc = 0.0f;

    #pragma unroll 1
    for (int outer = 0; outer < OUTER; outer++) {
        float4 m[U], g[U];
        // Front-batched independent 128-bit loads: MLP = 2*U = 8 per body.
        #pragma unroll
        for (int u = 0; u < U; u++) {
            const int i  = tid + (outer * U + u) * STRIDE;
            const int bt = i >> 10;
            const int f  = i & 1023;
            g[u] = __ldcs(&stft[(bt << 11) + f]);   // single-use: evict-first
            m[u] = __ldcs(&masks[i]);
        }
        #pragma unroll
        for (int u = 0; u < U; u++) {
            // first-max argmax over C=4 (strict > keeps earliest index)
            int j = 0;
            float best = g[u].x;
            if (g[u].y > best) { best = g[u].y; j = 1; }
            if (g[u].z > best) { best = g[u].z; j = 2; }
            if (g[u].w > best) { best = g[u].w; j = 3; }
            acc += fabsf(m[u].x - (j == 0 ? 1.0f : 0.0f));
            acc += fabsf(m[u].y - (j == 1 ? 1.0f : 0.0f));
            acc += fabsf(m[u].z - (j == 2 ? 1.0f : 0.0f));
            acc += fabsf(m[u].w - (j == 3 ? 1.0f : 0.0f));
        }
    }

    // warp reduce
    #pragma unroll
    for (int off = 16; off > 0; off >>= 1)
        acc += __shfl_xor_sync(0xFFFFFFFFu, acc, off);

    __shared__ float warp_sums[THREADS / 32];
    const int lane = threadIdx.x & 31;
    const int wid  = threadIdx.x >> 5;
    if (lane == 0) warp_sums[wid] = acc;
    __syncthreads();

    if (wid == 0) {
        float s = (lane < THREADS / 32) ? warp_sums[lane] : 0.0f;
        #pragma unroll
        for (int off = 8; off > 0; off >>= 1)
            s += __shfl_xor_sync(0xFFFFFFFFu, s, off);

        if (lane == 0) {
            atomicAdd(&g_partial, s);
            __threadfence();
            const unsigned done = atomicAdd(&g_count, 1u);
            if (done == (unsigned)gridDim.x - 1u) {
                // Last block: read-and-reset atomically so graph replays are
                // deterministic (g_partial/g_count return to 0 every call).
                const float total = atomicExch(&g_partial, 0.0f);
                atomicExch(&g_count, 0u);
                out[0] = total * INV_N;
            }
        }
    }
}

extern "C" void kernel_launch(void* const* d_in, const int* in_sizes, int n_in,
                              void* d_out, int out_size)
{
    const float4* masks = (const float4*)d_in[0];
    const float4* stft  = (const float4*)d_in[1];
    float* out = (float*)d_out;

    recon_loss_kernel<<<BLOCKS, THREADS>>>(masks, stft, out);
}